// round 4
// baseline (speedup 1.0000x reference)
#include <cuda_runtime.h>
#include <cstdint>
#include <cstddef>

typedef unsigned long long ull;

#define TS 2048
#define Y1_ELEMS ((size_t)TS * 64 * 256)

// scratch (allocation-free rule)
__device__ float g_gx[(size_t)TS * 64 * 1024];
__device__ float g_y0[(size_t)TS * 64 * 256];

__device__ __forceinline__ ull fma2(ull a, ull b, ull c) {
    ull d; asm("fma.rn.f32x2 %0,%1,%2,%3;" : "=l"(d) : "l"(a), "l"(b), "l"(c)); return d;
}
__device__ __forceinline__ ull add2(ull a, ull b) {
    ull d; asm("add.rn.f32x2 %0,%1,%2;" : "=l"(d) : "l"(a), "l"(b)); return d;
}
__device__ __forceinline__ ull pk(float lo, float hi) {
    ull r; asm("mov.b64 %0,{%1,%2};" : "=l"(r) : "f"(lo), "f"(hi)); return r;
}
__device__ __forceinline__ void upk(ull a, float& x, float& y) {
    asm("mov.b64 {%0,%1},%2;" : "=f"(x), "=f"(y) : "l"(a));
}
__device__ __forceinline__ ull dup2(float x) {
    ull r; asm("mov.b64 %0,{%1,%1};" : "=l"(r) : "f"(x)); return r;
}
__device__ __forceinline__ float sigf(float x) {
    return __fdividef(1.f, 1.f + __expf(-x));
}
__device__ __forceinline__ float tanhfast(float x) {
    // 2/(1+e^{-2x}) - 1 ; graceful at +-inf via __expf saturation
    return __fdividef(2.f, 1.f + __expf(-2.f * x)) - 1.f;
}

__device__ __forceinline__ void mwait(unsigned addr, int phase) {
    asm volatile(
        "{\n\t.reg .pred P;\n"
        "W%=:\n\t"
        "mbarrier.try_wait.parity.acquire.cluster.shared::cta.b64 P, [%0], %1;\n\t"
        "@!P bra W%=;\n\t}"
        :: "r"(addr), "r"((unsigned)phase) : "memory");
}

// ---------------------------------------------------------------------------
// GEMM: g_gx[m][n] = A_row(m) . W[:,n] + bias[n],  M = TS*64, N = 1024
// mode 0: A_row(m) = x + ((m&63)*TS + (m>>6))*128, K=128
// mode 1: A_row(m) = g_y0 + m*256,                 K=256
// ---------------------------------------------------------------------------
__global__ void __launch_bounds__(256, 1)
gemm_k(const float* __restrict__ A, const float* __restrict__ W,
       const float* __restrict__ bias, int K, int mode)
{
    __shared__ float As[16][132];
    __shared__ float Bs[16][128];

    const int tid = threadIdx.x;
    const int n0 = blockIdx.x * 128;
    const int m0 = blockIdx.y * 128;

    const int ar = tid >> 1;
    const int ac = (tid & 1) * 8;
    const int m = m0 + ar;
    const float* arow = mode ? (g_y0 + (size_t)m * 256)
                             : (A + ((size_t)(m & 63) * TS + (m >> 6)) * 128);
    const float* wp = W + (size_t)(tid >> 4) * 1024 + n0 + (tid & 15) * 8;

    const int tm = tid >> 4, tn = tid & 15;

    ull acc[8][4];
#pragma unroll
    for (int i = 0; i < 8; ++i)
#pragma unroll
        for (int j = 0; j < 4; ++j) acc[i][j] = 0ull;

#pragma unroll 1
    for (int k0 = 0; k0 < K; k0 += 16) {
        float4 a0 = *(const float4*)(arow + k0 + ac);
        float4 a1 = *(const float4*)(arow + k0 + ac + 4);
        float4 w0 = *(const float4*)(wp + (size_t)k0 * 1024);
        float4 w1 = *(const float4*)(wp + (size_t)k0 * 1024 + 4);
        __syncthreads();
        As[ac + 0][ar] = a0.x; As[ac + 1][ar] = a0.y;
        As[ac + 2][ar] = a0.z; As[ac + 3][ar] = a0.w;
        As[ac + 4][ar] = a1.x; As[ac + 5][ar] = a1.y;
        As[ac + 6][ar] = a1.z; As[ac + 7][ar] = a1.w;
        *(float4*)&Bs[tid >> 4][(tid & 15) * 8] = w0;
        *(float4*)&Bs[tid >> 4][(tid & 15) * 8 + 4] = w1;
        __syncthreads();
#pragma unroll
        for (int kk = 0; kk < 16; ++kk) {
            float4 av0 = *(const float4*)&As[kk][tm * 8];
            float4 av1 = *(const float4*)&As[kk][tm * 8 + 4];
            float av[8] = {av0.x, av0.y, av0.z, av0.w, av1.x, av1.y, av1.z, av1.w};
            const ull* bp = (const ull*)&Bs[kk][0];
            ull bv[4];
#pragma unroll
            for (int c = 0; c < 4; ++c) bv[c] = bp[tn * 4 + c];
#pragma unroll
            for (int r = 0; r < 8; ++r) {
                ull a2 = dup2(av[r]);
#pragma unroll
                for (int c = 0; c < 4; ++c) acc[r][c] = fma2(a2, bv[c], acc[r][c]);
            }
        }
    }

    float bb[8];
#pragma unroll
    for (int c = 0; c < 8; ++c) bb[c] = bias[n0 + tn * 8 + c];

#pragma unroll
    for (int r = 0; r < 8; ++r) {
        float v[8];
#pragma unroll
        for (int c = 0; c < 4; ++c) upk(acc[r][c], v[2 * c], v[2 * c + 1]);
#pragma unroll
        for (int c = 0; c < 8; ++c) v[c] += bb[c];
        float* op = g_gx + (size_t)(m0 + tm * 8 + r) * 1024 + n0 + tn * 8;
        *(float4*)op = make_float4(v[0], v[1], v[2], v[3]);
        *(float4*)(op + 4) = make_float4(v[4], v[5], v[6], v[7]);
    }
}

// ---------------------------------------------------------------------------
// Recurrence: 16 clusters x 8 CTAs, 4 batch elems per cluster.
// CTA rank r owns hidden units [r*32, r*32+32) for all 4 gates (128 cols).
// Thread (q = tid>>6, c = tid&63): gate = c>>4, j0 = r*32 + (c&15)*2;
// k-range [q*64, q*64+64), k-pair packed. w_hh slice lives in registers.
// Sync: per-CTA mbarrier full[2] (count 1024), double-buffered h via DSMEM.
// ---------------------------------------------------------------------------
__global__ void __launch_bounds__(256, 1) __cluster_dims__(8, 1, 1)
recur_k(const float* __restrict__ whh, float* __restrict__ out, int layer)
{
    __shared__ float2 hbuf[2][4][128];   // [buf][b][kpair]
    __shared__ ull red[4][4][128];       // [q][b][gate*32 + jl]
    __shared__ __align__(16) ull mbar[2];

    const int tid = threadIdx.x;
    const int q = tid >> 6;
    const int c = tid & 63;
    unsigned r;
    asm("mov.u32 %0, %%cluster_ctarank;" : "=r"(r));
    const int gb0 = (blockIdx.x >> 3) * 4;

    const int gate = c >> 4;
    const int j0 = (int)r * 32 + (c & 15) * 2;
    const int col = gate * 256 + j0;

    // w_hh slice -> registers, k-pair packed
    ull wa[32], wb[32];
#pragma unroll
    for (int kk = 0; kk < 32; ++kk) {
        const float* w0 = whh + (size_t)(q * 64 + 2 * kk) * 1024 + col;
        wa[kk] = pk(w0[0], w0[1024]);
        wb[kk] = pk(w0[1], w0[1025]);
    }

    // local smem addresses + hoisted mapa for all 8 ranks
    unsigned hb_loc = (unsigned)__cvta_generic_to_shared(&hbuf[0][0][0]);
    unsigned bar_loc = (unsigned)__cvta_generic_to_shared(&mbar[0]);
    unsigned hb_rem[8], bar_rem[8];
#pragma unroll
    for (int d = 0; d < 8; ++d) {
        asm("mapa.shared::cluster.u32 %0, %1, %2;" : "=r"(hb_rem[d]) : "r"(hb_loc), "r"(d));
        asm("mapa.shared::cluster.u32 %0, %1, %2;" : "=r"(bar_rem[d]) : "r"(bar_loc), "r"(d));
    }

    if (tid == 0) {
        asm volatile("mbarrier.init.shared.b64 [%0], %1;" :: "r"(bar_loc), "r"(1024u) : "memory");
        asm volatile("mbarrier.init.shared.b64 [%0], %1;" :: "r"(bar_loc + 8), "r"(1024u) : "memory");
        asm volatile("fence.mbarrier_init.release.cluster;" ::: "memory");
    }
    for (int i = tid; i < 2 * 4 * 128; i += 256)
        ((float2*)hbuf)[i] = make_float2(0.f, 0.f);
    __syncthreads();
    asm volatile("barrier.cluster.arrive.aligned;" ::: "memory");
    asm volatile("barrier.cluster.wait.aligned;" ::: "memory");

    const int eb = tid >> 5, ejl = tid & 31;   // epilogue mapping (tid<128)
    const int ej = (int)r * 32 + ejl;
    float cst = 0.f;
    float* yout = layer ? out : g_y0;
    float* hn = out + Y1_ELEMS + (size_t)layer * 16384;
    float* cn = out + Y1_ELEMS + 32768 + (size_t)layer * 16384;

    // remote byte offsets for this thread's h value (per buffer)
    const unsigned hoff0 = ((unsigned)(0 * 4 + eb) * 128 + (unsigned)(ej >> 1)) * 8u + (unsigned)(ej & 1) * 4u;
    const unsigned hoff1 = ((unsigned)(1 * 4 + eb) * 128 + (unsigned)(ej >> 1)) * 8u + (unsigned)(ej & 1) * 4u;

    int par0 = 0, par1 = 0;

#pragma unroll 1
    for (int s = 0; s < TS; ++s) {
        const int cur = s & 1;
        const int nxt = cur ^ 1;

        // gates_x prefetch (independent of hbuf; overlaps wait + matvec)
        float gf = 0.f, gi = 0.f, go = 0.f, gg = 0.f;
        if (tid < 128) {
            const float* gp = g_gx + ((size_t)(TS - 1 - s) * 64 + gb0 + eb) * 1024 + ej;
            gf = gp[0]; gi = gp[256]; go = gp[512]; gg = gp[768];
        }

        if (s) {
            if (cur == 0) { mwait(bar_loc, par0);     par0 ^= 1; }
            else          { mwait(bar_loc + 8, par1); par1 ^= 1; }
        }

        // matvec over this CTA's k-slice
#pragma unroll
        for (int b = 0; b < 4; ++b) {
            const ulonglong2* hp = (const ulonglong2*)&hbuf[cur][b][0] + q * 16;
            ull a0 = 0ull, a1 = 0ull;
#pragma unroll
            for (int kk = 0; kk < 16; ++kk) {
                ulonglong2 h2 = hp[kk];
                a0 = fma2(h2.x, wa[2 * kk], a0);
                a1 = fma2(h2.x, wb[2 * kk], a1);
                a0 = fma2(h2.y, wa[2 * kk + 1], a0);
                a1 = fma2(h2.y, wb[2 * kk + 1], a1);
            }
            ulonglong2 st; st.x = a0; st.y = a1;
            *(ulonglong2*)&red[q][b][gate * 32 + (c & 15) * 2] = st;
        }
        __syncthreads();

        if (tid < 128) {
            float gates[4];
#pragma unroll
            for (int g = 0; g < 4; ++g) {
                ull s01 = add2(red[0][eb][g * 32 + ejl], red[1][eb][g * 32 + ejl]);
                ull s23 = add2(red[2][eb][g * 32 + ejl], red[3][eb][g * 32 + ejl]);
                float lo, hi; upk(add2(s01, s23), lo, hi);
                gates[g] = lo + hi;
            }
            float f  = sigf(gates[0] + gf);
            float i  = sigf(gates[1] + gi);
            float o  = sigf(gates[2] + go);
            float g_ = tanhfast(gates[3] + gg);
            cst = f * cst + i * g_;
            float h1 = o * tanhfast(cst);

            yout[((size_t)s * 64 + gb0 + eb) * 256 + ej] = h1;

            if (s == TS - 1) {
                size_t hi_ = (size_t)(gb0 + eb) * 256 + ej;
                hn[hi_] = h1; cn[hi_] = cst;
            } else {
                const unsigned hoff = nxt ? hoff1 : hoff0;
                const unsigned boff = (unsigned)nxt * 8u;
#pragma unroll
                for (int d = 0; d < 8; ++d)
                    asm volatile("st.shared::cluster.f32 [%0], %1;"
                                 :: "r"(hb_rem[d] + hoff), "f"(h1) : "memory");
#pragma unroll
                for (int d = 0; d < 8; ++d)
                    asm volatile("mbarrier.arrive.release.cluster.shared::cluster.b64 _, [%0];"
                                 :: "r"(bar_rem[d] + boff) : "memory");
            }
        }
    }

    asm volatile("barrier.cluster.arrive.aligned;" ::: "memory");
    asm volatile("barrier.cluster.wait.aligned;" ::: "memory");
}

extern "C" void kernel_launch(void* const* d_in, const int* in_sizes, int n_in,
                              void* d_out, int out_size)
{
    const float* x    = (const float*)d_in[0];
    const float* wih0 = (const float*)d_in[1];
    const float* whh0 = (const float*)d_in[2];
    const float* b0   = (const float*)d_in[3];
    const float* wih1 = (const float*)d_in[4];
    const float* whh1 = (const float*)d_in[5];
    const float* b1   = (const float*)d_in[6];
    float* out = (float*)d_out;

    dim3 gg(8, 1024);
    gemm_k<<<gg, 256>>>(x, wih0, b0, 128, 0);
    recur_k<<<128, 256>>>(whh0, out, 0);
    gemm_k<<<gg, 256>>>(x, wih1, b1, 256, 1);
    recur_k<<<128, 256>>>(whh1, out, 1);
}

// round 5
// speedup vs baseline: 1.2588x; 1.2588x over previous
#include <cuda_runtime.h>
#include <cstdint>
#include <cstddef>

typedef unsigned long long ull;

#define TS 2048
#define Y1_ELEMS ((size_t)TS * 64 * 256)

// scratch (allocation-free rule)
__device__ float g_gx[(size_t)TS * 64 * 1024];
__device__ float g_y0[(size_t)TS * 64 * 256];

__device__ __forceinline__ ull fma2(ull a, ull b, ull c) {
    ull d; asm("fma.rn.f32x2 %0,%1,%2,%3;" : "=l"(d) : "l"(a), "l"(b), "l"(c)); return d;
}
__device__ __forceinline__ ull add2(ull a, ull b) {
    ull d; asm("add.rn.f32x2 %0,%1,%2;" : "=l"(d) : "l"(a), "l"(b)); return d;
}
__device__ __forceinline__ ull pk(float lo, float hi) {
    ull r; asm("mov.b64 %0,{%1,%2};" : "=l"(r) : "f"(lo), "f"(hi)); return r;
}
__device__ __forceinline__ void upk(ull a, float& x, float& y) {
    asm("mov.b64 {%0,%1},%2;" : "=f"(x), "=f"(y) : "l"(a));
}
__device__ __forceinline__ ull dup2(float x) {
    ull r; asm("mov.b64 %0,{%1,%1};" : "=l"(r) : "f"(x)); return r;
}
__device__ __forceinline__ float ex2f(float x) {
    float r; asm("ex2.approx.f32 %0,%1;" : "=f"(r) : "f"(x)); return r;
}
__device__ __forceinline__ float rcpf(float x) {
    float r; asm("rcp.approx.f32 %0,%1;" : "=f"(r) : "f"(x)); return r;
}
__device__ __forceinline__ float sigf(float x) {
    return rcpf(1.f + ex2f(-1.44269504f * x));
}
__device__ __forceinline__ float tanhap(float x) {
    float r; asm("tanh.approx.f32 %0,%1;" : "=f"(r) : "f"(x)); return r;
}

__device__ __forceinline__ void mwait(unsigned addr, int phase) {
    asm volatile(
        "{\n\t.reg .pred P;\n"
        "W%=:\n\t"
        "mbarrier.try_wait.parity.acquire.cluster.shared::cta.b64 P, [%0], %1;\n\t"
        "@!P bra W%=;\n\t}"
        :: "r"(addr), "r"((unsigned)phase) : "memory");
}

// ---------------------------------------------------------------------------
// GEMM: g_gx[m][n] = A_row(m) . W[:,n] + bias[n],  M = TS*64, N = 1024
// mode 0: A_row(m) = x + ((m&63)*TS + (m>>6))*128, K=128
// mode 1: A_row(m) = g_y0 + m*256,                 K=256
// ---------------------------------------------------------------------------
__global__ void __launch_bounds__(256, 1)
gemm_k(const float* __restrict__ A, const float* __restrict__ W,
       const float* __restrict__ bias, int K, int mode)
{
    __shared__ float As[16][132];
    __shared__ float Bs[16][128];

    const int tid = threadIdx.x;
    const int n0 = blockIdx.x * 128;
    const int m0 = blockIdx.y * 128;

    const int ar = tid >> 1;
    const int ac = (tid & 1) * 8;
    const int m = m0 + ar;
    const float* arow = mode ? (g_y0 + (size_t)m * 256)
                             : (A + ((size_t)(m & 63) * TS + (m >> 6)) * 128);
    const float* wp = W + (size_t)(tid >> 4) * 1024 + n0 + (tid & 15) * 8;

    const int tm = tid >> 4, tn = tid & 15;

    ull acc[8][4];
#pragma unroll
    for (int i = 0; i < 8; ++i)
#pragma unroll
        for (int j = 0; j < 4; ++j) acc[i][j] = 0ull;

#pragma unroll 1
    for (int k0 = 0; k0 < K; k0 += 16) {
        float4 a0 = *(const float4*)(arow + k0 + ac);
        float4 a1 = *(const float4*)(arow + k0 + ac + 4);
        float4 w0 = *(const float4*)(wp + (size_t)k0 * 1024);
        float4 w1 = *(const float4*)(wp + (size_t)k0 * 1024 + 4);
        __syncthreads();
        As[ac + 0][ar] = a0.x; As[ac + 1][ar] = a0.y;
        As[ac + 2][ar] = a0.z; As[ac + 3][ar] = a0.w;
        As[ac + 4][ar] = a1.x; As[ac + 5][ar] = a1.y;
        As[ac + 6][ar] = a1.z; As[ac + 7][ar] = a1.w;
        *(float4*)&Bs[tid >> 4][(tid & 15) * 8] = w0;
        *(float4*)&Bs[tid >> 4][(tid & 15) * 8 + 4] = w1;
        __syncthreads();
#pragma unroll
        for (int kk = 0; kk < 16; ++kk) {
            float4 av0 = *(const float4*)&As[kk][tm * 8];
            float4 av1 = *(const float4*)&As[kk][tm * 8 + 4];
            float av[8] = {av0.x, av0.y, av0.z, av0.w, av1.x, av1.y, av1.z, av1.w};
            const ull* bp = (const ull*)&Bs[kk][0];
            ull bv[4];
#pragma unroll
            for (int c = 0; c < 4; ++c) bv[c] = bp[tn * 4 + c];
#pragma unroll
            for (int r = 0; r < 8; ++r) {
                ull a2 = dup2(av[r]);
#pragma unroll
                for (int c = 0; c < 4; ++c) acc[r][c] = fma2(a2, bv[c], acc[r][c]);
            }
        }
    }

    float bb[8];
#pragma unroll
    for (int c = 0; c < 8; ++c) bb[c] = bias[n0 + tn * 8 + c];

#pragma unroll
    for (int r = 0; r < 8; ++r) {
        float v[8];
#pragma unroll
        for (int c = 0; c < 4; ++c) upk(acc[r][c], v[2 * c], v[2 * c + 1]);
#pragma unroll
        for (int c = 0; c < 8; ++c) v[c] += bb[c];
        float* op = g_gx + (size_t)(m0 + tm * 8 + r) * 1024 + n0 + tn * 8;
        *(float4*)op = make_float4(v[0], v[1], v[2], v[3]);
        *(float4*)(op + 4) = make_float4(v[4], v[5], v[6], v[7]);
    }
}

// ---------------------------------------------------------------------------
// Recurrence: 16 clusters x 8 CTAs, 4 batch elems per cluster.
// CTA rank r owns hidden units [r*32, r*32+32) for all 4 gates.
// Warp w owns j in {r*32+w*4 .. +3}. Lane = jl*8 + g*2 + kh:
//   jl = hidden-unit-local (0..3), g = gate (0..3), kh = k-half (0..1).
// Each lane: 1 gate-column, 128 k (64 k-pairs) in registers.
// Reduce = 1 shfl; activations parallel per gate-lane; gather via warp smem.
// Sync: one bar.sync + 8 elected remote mbarrier arrives per step.
// ---------------------------------------------------------------------------
__global__ void __launch_bounds__(256, 1) __cluster_dims__(8, 1, 1)
recur_k(const float* __restrict__ whh, float* __restrict__ out, int layer)
{
    // kpair index padded: pi = p + (p>>6)*2  (kh=1 block starts at 66, 16B aligned,
    // different bank than kh=0 block)
    __shared__ float2 hbuf[2][4][132];
    __shared__ float gsm[8][4][4][4];   // [warp][gate][jl][batch]
    __shared__ __align__(16) ull mbar[2];

    const int tid  = threadIdx.x;
    const int w    = tid >> 5;
    const int lane = tid & 31;
    const int jl   = lane >> 3;
    const int g    = (lane >> 1) & 3;
    const int kh   = lane & 1;
    unsigned r;
    asm("mov.u32 %0, %%cluster_ctarank;" : "=r"(r));
    const int gb0 = (blockIdx.x >> 3) * 4;

    const int j   = (int)r * 32 + w * 4 + jl;
    const int col = g * 256 + j;

    // weights: 64 k-pairs for this lane's column, k-range [kh*128, kh*128+128)
    ull wa[64];
#pragma unroll
    for (int kk = 0; kk < 64; ++kk) {
        const float* w0 = whh + (size_t)(kh * 128 + 2 * kk) * 1024 + col;
        wa[kk] = pk(w0[0], w0[1024]);
    }

    unsigned hb_loc  = (unsigned)__cvta_generic_to_shared(&hbuf[0][0][0]);
    unsigned bar_loc = (unsigned)__cvta_generic_to_shared(&mbar[0]);
    unsigned hb_rem[8], bar_rem[8];
#pragma unroll
    for (int d = 0; d < 8; ++d) {
        asm("mapa.shared::cluster.u32 %0, %1, %2;" : "=r"(hb_rem[d]) : "r"(hb_loc), "r"(d));
        asm("mapa.shared::cluster.u32 %0, %1, %2;" : "=r"(bar_rem[d]) : "r"(bar_loc), "r"(d));
    }

    if (tid == 0) {
        asm volatile("mbarrier.init.shared.b64 [%0], %1;" :: "r"(bar_loc), "r"(8u) : "memory");
        asm volatile("mbarrier.init.shared.b64 [%0], %1;" :: "r"(bar_loc + 8), "r"(8u) : "memory");
        asm volatile("fence.mbarrier_init.release.cluster;" ::: "memory");
    }
    for (int i = tid; i < 2 * 4 * 132; i += 256)
        ((float2*)hbuf)[i] = make_float2(0.f, 0.f);
    __syncthreads();
    asm volatile("barrier.cluster.arrive.aligned;" ::: "memory");
    asm volatile("barrier.cluster.wait.aligned;" ::: "memory");

    float cst = 0.f;
    float* yout = layer ? out : g_y0;
    float* hn = out + Y1_ELEMS + (size_t)layer * 16384;
    float* cn = out + Y1_ELEMS + 32768 + (size_t)layer * 16384;

    // remote store offsets for this task-lane's h value (task lanes: kh==0, b=g)
    const int tb = g;                 // batch handled in c-update phase
    const int pj = j >> 1;
    const int pi = pj + ((pj >> 6) << 1);
    const unsigned hoff0 = ((unsigned)(0 * 4 + tb) * 132 + (unsigned)pi) * 8u + (unsigned)(j & 1) * 4u;
    const unsigned hoff1 = ((unsigned)(1 * 4 + tb) * 132 + (unsigned)pi) * 8u + (unsigned)(j & 1) * 4u;

    // gates_x software pipeline (kh==0 lanes): values for step s in gxr[]
    float gxr[4], gxn[4];
    if (kh == 0) {
        const float* gp = g_gx + ((size_t)(TS - 1) * 64 + gb0) * 1024 + col;
#pragma unroll
        for (int b = 0; b < 4; ++b) gxr[b] = __ldg(gp + (size_t)b * 1024);
    }

    int par0 = 0, par1 = 0;

#pragma unroll 1
    for (int s = 0; s < TS; ++s) {
        const int cur = s & 1;
        const int nxt = cur ^ 1;

        // prefetch next step's gates_x (hidden behind wait + matvec)
        if (kh == 0 && s + 1 < TS) {
            const float* gp = g_gx + ((size_t)(TS - 2 - s) * 64 + gb0) * 1024 + col;
#pragma unroll
            for (int b = 0; b < 4; ++b) gxn[b] = __ldg(gp + (size_t)b * 1024);
        }

        if (s) {
            if (cur == 0) { mwait(bar_loc, par0);     par0 ^= 1; }
            else          { mwait(bar_loc + 8, par1); par1 ^= 1; }
        }

        // matvec: 4 batches, 64 k-pairs each
        ull acc[4];
#pragma unroll
        for (int b = 0; b < 4; ++b) {
            const ulonglong2* hp = (const ulonglong2*)&hbuf[cur][b][kh * 66];
            ull a = 0ull;
#pragma unroll
            for (int kk = 0; kk < 32; ++kk) {
                ulonglong2 h2 = hp[kk];
                a = fma2(h2.x, wa[2 * kk], a);
                a = fma2(h2.y, wa[2 * kk + 1], a);
            }
            acc[b] = a;
        }

        // k-half reduce (1 shfl per batch) + horizontal
        float gv[4];
#pragma unroll
        for (int b = 0; b < 4; ++b) {
            ull o = __shfl_xor_sync(0xffffffffu, acc[b], 1);
            float lo, hi; upk(add2(acc[b], o), lo, hi);
            gv[b] = lo + hi;
        }

        if (kh == 0) {
            // activations for my gate, all 4 batches
            float av[4];
            if (g == 3) {
#pragma unroll
                for (int b = 0; b < 4; ++b) av[b] = tanhap(gv[b] + gxr[b]);
            } else {
#pragma unroll
                for (int b = 0; b < 4; ++b) av[b] = sigf(gv[b] + gxr[b]);
            }
            *(float4*)&gsm[w][g][jl][0] = make_float4(av[0], av[1], av[2], av[3]);
        }
        __syncwarp();

        if (kh == 0) {
            // task lane: (jl, batch tb) — gather 4 gates, update state
            float f_  = gsm[w][0][jl][tb];
            float i_  = gsm[w][1][jl][tb];
            float o_  = gsm[w][2][jl][tb];
            float g_  = gsm[w][3][jl][tb];
            cst = f_ * cst + i_ * g_;
            float h1 = o_ * tanhap(cst);

            yout[((size_t)s * 64 + gb0 + tb) * 256 + j] = h1;

            if (s == TS - 1) {
                size_t hi_ = (size_t)(gb0 + tb) * 256 + j;
                hn[hi_] = h1; cn[hi_] = cst;
            } else {
                const unsigned hoff = nxt ? hoff1 : hoff0;
#pragma unroll
                for (int d = 0; d < 8; ++d)
                    asm volatile("st.shared::cluster.f32 [%0], %1;"
                                 :: "r"(hb_rem[d] + hoff), "f"(h1) : "memory");
            }
#pragma unroll
            for (int b = 0; b < 4; ++b) gxr[b] = gxn[b];
        }

        __syncthreads();
        if (s < TS - 1 && tid < 8)
            asm volatile("mbarrier.arrive.release.cluster.shared::cluster.b64 _, [%0];"
                         :: "r"(bar_rem[tid] + (unsigned)nxt * 8u) : "memory");
    }

    asm volatile("barrier.cluster.arrive.aligned;" ::: "memory");
    asm volatile("barrier.cluster.wait.aligned;" ::: "memory");
}

extern "C" void kernel_launch(void* const* d_in, const int* in_sizes, int n_in,
                              void* d_out, int out_size)
{
    const float* x    = (const float*)d_in[0];
    const float* wih0 = (const float*)d_in[1];
    const float* whh0 = (const float*)d_in[2];
    const float* b0   = (const float*)d_in[3];
    const float* wih1 = (const float*)d_in[4];
    const float* whh1 = (const float*)d_in[5];
    const float* b1   = (const float*)d_in[6];
    float* out = (float*)d_out;

    dim3 gg(8, 1024);
    gemm_k<<<gg, 256>>>(x, wih0, b0, 128, 0);
    recur_k<<<128, 256>>>(whh0, out, 0);
    gemm_k<<<gg, 256>>>(x, wih1, b1, 256, 1);
    recur_k<<<128, 256>>>(whh1, out, 1);
}

// round 6
// speedup vs baseline: 1.3511x; 1.0733x over previous
#include <cuda_runtime.h>
#include <cstdint>
#include <cstddef>

typedef unsigned long long ull;

#define TS 2048
#define Y1_ELEMS ((size_t)TS * 64 * 256)

// scratch (allocation-free rule)
__device__ float g_gx[(size_t)TS * 64 * 1024];
__device__ float g_y0[(size_t)TS * 64 * 256];

__device__ __forceinline__ ull fma2(ull a, ull b, ull c) {
    ull d; asm("fma.rn.f32x2 %0,%1,%2,%3;" : "=l"(d) : "l"(a), "l"(b), "l"(c)); return d;
}
__device__ __forceinline__ ull add2(ull a, ull b) {
    ull d; asm("add.rn.f32x2 %0,%1,%2;" : "=l"(d) : "l"(a), "l"(b)); return d;
}
__device__ __forceinline__ ull pk(float lo, float hi) {
    ull r; asm("mov.b64 %0,{%1,%2};" : "=l"(r) : "f"(lo), "f"(hi)); return r;
}
__device__ __forceinline__ void upk(ull a, float& x, float& y) {
    asm("mov.b64 {%0,%1},%2;" : "=f"(x), "=f"(y) : "l"(a));
}
__device__ __forceinline__ ull dup2(float x) {
    ull r; asm("mov.b64 %0,{%1,%1};" : "=l"(r) : "f"(x)); return r;
}
__device__ __forceinline__ float ex2f(float x) {
    float r; asm("ex2.approx.f32 %0,%1;" : "=f"(r) : "f"(x)); return r;
}
__device__ __forceinline__ float rcpf(float x) {
    float r; asm("rcp.approx.f32 %0,%1;" : "=f"(r) : "f"(x)); return r;
}
__device__ __forceinline__ float sigf(float x) {
    return rcpf(1.f + ex2f(-1.44269504f * x));
}
__device__ __forceinline__ float tanhap(float x) {
    float r; asm("tanh.approx.f32 %0,%1;" : "=f"(r) : "f"(x)); return r;
}

__device__ __forceinline__ void mwait(unsigned addr, int phase) {
    asm volatile(
        "{\n\t.reg .pred P;\n"
        "W%=:\n\t"
        "mbarrier.try_wait.parity.acquire.cluster.shared::cta.b64 P, [%0], %1;\n\t"
        "@!P bra W%=;\n\t}"
        :: "r"(addr), "r"((unsigned)phase) : "memory");
}

// ---------------------------------------------------------------------------
// GEMM: g_gx[m][n] = A_row(m) . W[:,n] + bias[n],  M = TS*64, N = 1024
// mode 0: A_row(m) = x + ((m&63)*TS + (m>>6))*128, K=128
// mode 1: A_row(m) = g_y0 + m*256,                 K=256
// ---------------------------------------------------------------------------
__global__ void __launch_bounds__(256, 1)
gemm_k(const float* __restrict__ A, const float* __restrict__ W,
       const float* __restrict__ bias, int K, int mode)
{
    __shared__ float As[16][132];
    __shared__ float Bs[16][128];

    const int tid = threadIdx.x;
    const int n0 = blockIdx.x * 128;
    const int m0 = blockIdx.y * 128;

    const int ar = tid >> 1;
    const int ac = (tid & 1) * 8;
    const int m = m0 + ar;
    const float* arow = mode ? (g_y0 + (size_t)m * 256)
                             : (A + ((size_t)(m & 63) * TS + (m >> 6)) * 128);
    const float* wp = W + (size_t)(tid >> 4) * 1024 + n0 + (tid & 15) * 8;

    const int tm = tid >> 4, tn = tid & 15;

    ull acc[8][4];
#pragma unroll
    for (int i = 0; i < 8; ++i)
#pragma unroll
        for (int j = 0; j < 4; ++j) acc[i][j] = 0ull;

#pragma unroll 1
    for (int k0 = 0; k0 < K; k0 += 16) {
        float4 a0 = *(const float4*)(arow + k0 + ac);
        float4 a1 = *(const float4*)(arow + k0 + ac + 4);
        float4 w0 = *(const float4*)(wp + (size_t)k0 * 1024);
        float4 w1 = *(const float4*)(wp + (size_t)k0 * 1024 + 4);
        __syncthreads();
        As[ac + 0][ar] = a0.x; As[ac + 1][ar] = a0.y;
        As[ac + 2][ar] = a0.z; As[ac + 3][ar] = a0.w;
        As[ac + 4][ar] = a1.x; As[ac + 5][ar] = a1.y;
        As[ac + 6][ar] = a1.z; As[ac + 7][ar] = a1.w;
        *(float4*)&Bs[tid >> 4][(tid & 15) * 8] = w0;
        *(float4*)&Bs[tid >> 4][(tid & 15) * 8 + 4] = w1;
        __syncthreads();
#pragma unroll
        for (int kk = 0; kk < 16; ++kk) {
            float4 av0 = *(const float4*)&As[kk][tm * 8];
            float4 av1 = *(const float4*)&As[kk][tm * 8 + 4];
            float av[8] = {av0.x, av0.y, av0.z, av0.w, av1.x, av1.y, av1.z, av1.w};
            const ull* bp = (const ull*)&Bs[kk][0];
            ull bv[4];
#pragma unroll
            for (int c = 0; c < 4; ++c) bv[c] = bp[tn * 4 + c];
#pragma unroll
            for (int r = 0; r < 8; ++r) {
                ull a2 = dup2(av[r]);
#pragma unroll
                for (int c = 0; c < 4; ++c) acc[r][c] = fma2(a2, bv[c], acc[r][c]);
            }
        }
    }

    float bb[8];
#pragma unroll
    for (int c = 0; c < 8; ++c) bb[c] = bias[n0 + tn * 8 + c];

#pragma unroll
    for (int r = 0; r < 8; ++r) {
        float v[8];
#pragma unroll
        for (int c = 0; c < 4; ++c) upk(acc[r][c], v[2 * c], v[2 * c + 1]);
#pragma unroll
        for (int c = 0; c < 8; ++c) v[c] += bb[c];
        float* op = g_gx + (size_t)(m0 + tm * 8 + r) * 1024 + n0 + tn * 8;
        *(float4*)op = make_float4(v[0], v[1], v[2], v[3]);
        *(float4*)(op + 4) = make_float4(v[4], v[5], v[6], v[7]);
    }
}

// ---------------------------------------------------------------------------
// Recurrence: 16 clusters x 8 CTAs, 4 batch elems per cluster.
// CTA rank r owns hidden units [r*32, r*32+32). Warp w owns units
// jw = r*32 + w*4 + u (u=0..3), ALL 4 gates, ALL 4 batches, all k — warp
// self-contained. Lane l owns k-chunk {4l..4l+3} U {128+4l..128+4l+3}
// (coalesced LDS) for all 16 columns (8 col-pairs packed in f32x2).
// Reduce = 5-round reduce-scatter butterfly; final lane l holds the full
// k-sum for (cp = l>>2, b = l&3). Col-pairs: gp=0 -> gates(f,i),
// gp=1 -> gates(o,g). Epilogue: 2 activations + 1 shfl; gp=0 lanes carry c.
// Sync: one bar.sync + 8 elected remote mbarrier arrives per step.
// ---------------------------------------------------------------------------
__global__ void __launch_bounds__(256, 1) __cluster_dims__(8, 1, 1)
recur_k(const float* __restrict__ whh, float* __restrict__ out, int layer)
{
    __shared__ float hbuf[2][4][256];    // [buf][b][k] — coalesced reads
    __shared__ __align__(16) ull mbar[2];

    const int tid  = threadIdx.x;
    const int w    = tid >> 5;
    const int lane = tid & 31;
    unsigned r;
    asm("mov.u32 %0, %%cluster_ctarank;" : "=r"(r));
    const int gb0 = (blockIdx.x >> 3) * 4;

    // this lane's epilogue identity
    const int cp = lane >> 2;          // col-pair 0..7
    const int b  = lane & 3;           // batch 0..3
    const int gp = cp & 1;             // gate-pair: 0 -> (f,i), 1 -> (o,g)
    const int u  = cp >> 1;            // unit-local 0..3
    const int jj = (int)r * 32 + w * 4 + u;
    const int colA = (2 * gp) * 256 + jj;   // first gate col of the pair

    // weights: wreg[cp][kk], k(kk) = kk<4 ? 4*lane+kk : 128+4*lane+(kk-4)
    ull wreg[8][8];
#pragma unroll
    for (int cpi = 0; cpi < 8; ++cpi) {
        const int ui = cpi >> 1, gpi = cpi & 1;
        const int cA = (2 * gpi) * 256 + (int)r * 32 + w * 4 + ui;
#pragma unroll
        for (int kk = 0; kk < 8; ++kk) {
            const int k = (kk < 4) ? (4 * lane + kk) : (128 + 4 * lane + kk - 4);
            const float* wp = whh + (size_t)k * 1024 + cA;
            wreg[cpi][kk] = pk(wp[0], wp[256]);
        }
    }

    unsigned hb_loc  = (unsigned)__cvta_generic_to_shared(&hbuf[0][0][0]);
    unsigned bar_loc = (unsigned)__cvta_generic_to_shared(&mbar[0]);
    unsigned bar_mine = 0;
    if (tid < 8)
        asm("mapa.shared::cluster.u32 %0, %1, %2;" : "=r"(bar_mine) : "r"(bar_loc), "r"(tid));

    if (tid == 0) {
        asm volatile("mbarrier.init.shared.b64 [%0], %1;" :: "r"(bar_loc), "r"(8u) : "memory");
        asm volatile("mbarrier.init.shared.b64 [%0], %1;" :: "r"(bar_loc + 8), "r"(8u) : "memory");
        asm volatile("fence.mbarrier_init.release.cluster;" ::: "memory");
    }
    for (int i = tid; i < 2 * 4 * 256; i += 256)
        ((float*)hbuf)[i] = 0.f;
    __syncthreads();
    asm volatile("barrier.cluster.arrive.aligned;" ::: "memory");
    asm volatile("barrier.cluster.wait.aligned;" ::: "memory");

    float cst = 0.f;
    float* yout = layer ? out : g_y0;
    float* hn = out + Y1_ELEMS + (size_t)layer * 16384;
    float* cn = out + Y1_ELEMS + 32768 + (size_t)layer * 16384;

    // gates_x pipeline: gxr = packed (colA, colA+256) for step s
    ull gxr, gxn = 0ull;
    {
        const float* gpx = g_gx + ((size_t)(TS - 1) * 64 + gb0 + b) * 1024 + colA;
        gxr = pk(__ldg(gpx), __ldg(gpx + 256));
    }

    int par0 = 0, par1 = 0;

#pragma unroll 1
    for (int s = 0; s < TS; ++s) {
        const int cur = s & 1;
        const int nxt = cur ^ 1;

        // prefetch next step's gates_x (off critical path)
        if (s + 1 < TS) {
            const float* gpx = g_gx + ((size_t)(TS - 2 - s) * 64 + gb0 + b) * 1024 + colA;
            gxn = pk(__ldg(gpx), __ldg(gpx + 256));
        }

        if (s) {
            if (cur == 0) { mwait(bar_loc, par0);     par0 ^= 1; }
            else          { mwait(bar_loc + 8, par1); par1 ^= 1; }
        }

        // matvec: v[cp*4 + bb] accumulates this lane's k-chunk
        ull v[32];
#pragma unroll
        for (int i = 0; i < 32; ++i) v[i] = 0ull;
#pragma unroll
        for (int bb = 0; bb < 4; ++bb) {
            float4 hA = *(const float4*)&hbuf[cur][bb][lane * 4];
            float4 hB = *(const float4*)&hbuf[cur][bb][128 + lane * 4];
            float h8[8] = {hA.x, hA.y, hA.z, hA.w, hB.x, hB.y, hB.z, hB.w};
#pragma unroll
            for (int kk = 0; kk < 8; ++kk) {
                ull hd = dup2(h8[kk]);
#pragma unroll
                for (int cpi = 0; cpi < 8; ++cpi)
                    v[cpi * 4 + bb] = fma2(hd, wreg[cpi][kk], v[cpi * 4 + bb]);
            }
        }

        // reduce-scatter butterfly: after round t, entries with current bit0
        // resolved to lane bit t. Final: v[0] = full sum for (cp=l>>2, b=l&3).
#pragma unroll
        for (int t = 0; t < 5; ++t) {
            const int mybit = (lane >> t) & 1;
            const int n = 32 >> t;
#pragma unroll
            for (int i = 0; i < 16; ++i) {
                if (i < (n >> 1)) {
                    ull lo = v[2 * i], hi = v[2 * i + 1];
                    ull send = mybit ? lo : hi;
                    ull recv = __shfl_xor_sync(0xffffffffu, send, 1 << t);
                    v[i] = add2(mybit ? hi : lo, recv);
                }
            }
        }

        // epilogue
        {
            float p0, p1;
            upk(add2(v[0], gxr), p0, p1);
            float a0 = sigf(p0);
            float a1 = gp ? tanhap(p1) : sigf(p1);   // gp0:(f,i)  gp1:(σo,g̃)
            ull other = __shfl_xor_sync(0xffffffffu, pk(a0, a1), 4);
            if (gp == 0) {
                float so, tg; upk(other, so, tg);
                cst = a0 * cst + a1 * tg;
                float h1 = so * tanhap(cst);

                yout[((size_t)s * 64 + gb0 + b) * 256 + jj] = h1;
                if (s == TS - 1) {
                    size_t hi_ = (size_t)(gb0 + b) * 256 + jj;
                    hn[hi_] = h1; cn[hi_] = cst;
                } else {
                    const unsigned hoff = hb_loc +
                        (unsigned)(((nxt * 4 + b) * 256 + jj) * 4);
#pragma unroll
                    for (int d = 0; d < 8; ++d) {
                        unsigned ra;
                        asm("mapa.shared::cluster.u32 %0, %1, %2;" : "=r"(ra) : "r"(hoff), "r"(d));
                        asm volatile("st.shared::cluster.f32 [%0], %1;"
                                     :: "r"(ra), "f"(h1) : "memory");
                    }
                }
            }
        }
        gxr = gxn;

        __syncthreads();
        if (s < TS - 1 && tid < 8)
            asm volatile("mbarrier.arrive.release.cluster.shared::cluster.b64 _, [%0];"
                         :: "r"(bar_mine + (unsigned)nxt * 8u) : "memory");
    }

    asm volatile("barrier.cluster.arrive.aligned;" ::: "memory");
    asm volatile("barrier.cluster.wait.aligned;" ::: "memory");
}

extern "C" void kernel_launch(void* const* d_in, const int* in_sizes, int n_in,
                              void* d_out, int out_size)
{
    const float* x    = (const float*)d_in[0];
    const float* wih0 = (const float*)d_in[1];
    const float* whh0 = (const float*)d_in[2];
    const float* b0   = (const float*)d_in[3];
    const float* wih1 = (const float*)d_in[4];
    const float* whh1 = (const float*)d_in[5];
    const float* b1   = (const float*)d_in[6];
    float* out = (float*)d_out;

    dim3 gg(8, 1024);
    gemm_k<<<gg, 256>>>(x, wih0, b0, 128, 0);
    recur_k<<<128, 256>>>(whh0, out, 0);
    gemm_k<<<gg, 256>>>(x, wih1, b1, 256, 1);
    recur_k<<<128, 256>>>(whh1, out, 1);
}